// round 12
// baseline (speedup 1.0000x reference)
#include <cuda_runtime.h>
#include <cuda_fp16.h>
#include <cstdint>

#define D_IN   1024
#define D_OUT  1024
#define RANK   16
#define M_TOTAL 32768
#define BM 128
#define BN 128
#define BKH 64                    // halves per k-tile (128 B per row)
#define NSTAGE 3
#define NT (D_IN / BKH)           // 16
#define STAGE_BYTES 32768         // A 16 KB + B 16 KB
#define SMEM_BYTES (NSTAGE * STAGE_BYTES + 1024)

// fp16 effective weight (static __device__ per allocation rules)
__device__ __half g_wh[(size_t)D_OUT * D_IN];    // 2 MB

// ---------------------------------------------------------------------------
// Prep: w_half[o][d] = fp16_rn( (mag[o]/||W_o + 2*B_o A||) * (W[o][d] + 2*sum_r B[o][r]*A[r][d]) )
// ---------------------------------------------------------------------------
__global__ void prep_kernel(const float* __restrict__ W, const float* __restrict__ A,
                            const float* __restrict__ Bw, const float* __restrict__ mag) {
    int o = blockIdx.x;
    __shared__ float bvals[RANK];
    __shared__ float red[8];
    int t = threadIdx.x;  // 256
    if (t < RANK) bvals[t] = 2.0f * Bw[o * RANK + t];
    __syncthreads();

    float we[4];
    float local = 0.f;
#pragma unroll
    for (int i = 0; i < 4; i++) {
        int d = t + i * 256;
        float acc = W[o * D_IN + d];
#pragma unroll
        for (int r = 0; r < RANK; r++) acc = fmaf(bvals[r], A[r * D_IN + d], acc);
        we[i] = acc;
        local = fmaf(acc, acc, local);
    }
#pragma unroll
    for (int s = 16; s; s >>= 1) local += __shfl_xor_sync(0xffffffffu, local, s);
    if ((t & 31) == 0) red[t >> 5] = local;
    __syncthreads();
    if (t < 8) {
        float v = red[t];
#pragma unroll
        for (int s = 4; s; s >>= 1) v += __shfl_xor_sync(0xffu, v, s);
        if (t == 0) red[0] = v;
    }
    __syncthreads();
    float mns = mag[o] / sqrtf(red[0]);
#pragma unroll
    for (int i = 0; i < 4; i++) {
        int d = t + i * 256;
        g_wh[(size_t)o * D_IN + d] = __float2half_rn(mns * we[i]);
    }
}

// ---------------------------------------------------------------------------
// helpers
// ---------------------------------------------------------------------------
__device__ __forceinline__ uint32_t smem_u32(const void* p) {
    uint32_t a;
    asm("{ .reg .u64 t; cvta.to.shared.u64 t, %1; cvt.u32.u64 %0, t; }" : "=r"(a) : "l"(p));
    return a;
}
__device__ __forceinline__ void cp_async16(uint32_t s, const void* g) {
    asm volatile("cp.async.cg.shared.global [%0], [%1], 16;\n" :: "r"(s), "l"(g));
}
__device__ __forceinline__ void ldsm_x4(uint32_t* r, uint32_t addr) {
    asm volatile("ldmatrix.sync.aligned.m8n8.x4.shared.b16 {%0,%1,%2,%3}, [%4];"
                 : "=r"(r[0]), "=r"(r[1]), "=r"(r[2]), "=r"(r[3]) : "r"(addr));
}

// ---------------------------------------------------------------------------
// fp16 GEMM with fused A conversion:
// out[M,N] = fp16(X)[M,K] @ Wh[N,K]^T   (128x128x64 tiles, ldmatrix + m16n8k16)
// A path: LDG fp32 (kt+2) -> regs -> cvt+STS fp16 (kt+1) -> compute (kt).
// B path: cp.async fp16 as before. No separate conversion pass.
// ---------------------------------------------------------------------------
__global__ __launch_bounds__(256) void gemm_f16(const float* __restrict__ X,
                                                float* __restrict__ out) {
    extern __shared__ __align__(16) char smem[];
    const uint32_t sbuf = (smem_u32(smem) + 1023u) & ~1023u;

    const int tid = threadIdx.x;
    const int lane = tid & 31;
    const int warp = tid >> 5;
    const int warpM = warp & 1;   // 2 warps over M: 64 rows each
    const int warpN = warp >> 1;  // 4 warps over N: 32 cols each
    const int bM = blockIdx.y * BM;
    const int bN = blockIdx.x * BN;

    const int lrow = lane & 7;    // row-within-matrix for ldmatrix address
    const int lm = lane >> 3;     // matrix id 0..3

    // this thread's 4 A-chunks (16B fp16 each = 8 floats source)
    int arow[4], ach[4];
#pragma unroll
    for (int i = 0; i < 4; i++) {
        int cc = tid + i * 256;
        arow[i] = cc >> 3; ach[i] = cc & 7;
    }

    float4 arg[4][2];  // prefetched fp32 A for one k-tile (32 regs)

    auto ldgA = [&](int kt) {
#pragma unroll
        for (int i = 0; i < 4; i++) {
            const float4* p = (const float4*)(X + (size_t)(bM + arow[i]) * D_IN + kt * BKH + ach[i] * 8);
            arg[i][0] = __ldg(p);
            arg[i][1] = __ldg(p + 1);
        }
    };
    auto stsA = [&](int s) {
        const uint32_t abase = sbuf + (uint32_t)s * STAGE_BYTES;
#pragma unroll
        for (int i = 0; i < 4; i++) {
            __half2 h0 = __floats2half2_rn(arg[i][0].x, arg[i][0].y);
            __half2 h1 = __floats2half2_rn(arg[i][0].z, arg[i][0].w);
            __half2 h2 = __floats2half2_rn(arg[i][1].x, arg[i][1].y);
            __half2 h3 = __floats2half2_rn(arg[i][1].z, arg[i][1].w);
            uint4 v;
            v.x = *(uint32_t*)&h0; v.y = *(uint32_t*)&h1;
            v.z = *(uint32_t*)&h2; v.w = *(uint32_t*)&h3;
            uint32_t off = (uint32_t)(arow[i] * 128 + ((ach[i] ^ (arow[i] & 7)) << 4));
            asm volatile("st.shared.v4.b32 [%0], {%1,%2,%3,%4};"
                         :: "r"(abase + off), "r"(v.x), "r"(v.y), "r"(v.z), "r"(v.w));
        }
    };
    auto issueB = [&](int kt, int s) {
        const uint32_t bbase = sbuf + (uint32_t)s * STAGE_BYTES + 16384u;
#pragma unroll
        for (int i = 0; i < 4; i++) {
            int cc = tid + i * 256;
            int row = cc >> 3, ch = cc & 7;
            uint32_t off = (uint32_t)(row * 128 + ((ch ^ (row & 7)) << 4));
            cp_async16(bbase + off, g_wh + (size_t)(bN + row) * D_IN + kt * BKH + ch * 8);
        }
        asm volatile("cp.async.commit_group;\n" ::: "memory");
    };

    float c[4][4][4];
#pragma unroll
    for (int i = 0; i < 4; i++)
#pragma unroll
        for (int j = 0; j < 4; j++)
#pragma unroll
            for (int k = 0; k < 4; k++) c[i][j][k] = 0.f;

    // prologue
    ldgA(0);
    issueB(0, 0);
    stsA(0);           // stalls once on first LDG arrival
    ldgA(1);
    issueB(1, 1);

    // per-lane invariant row offsets (row offsets are multiples of 8 -> row&7 == lrow)
    const uint32_t aRowOff = (uint32_t)((warpM * 64 + ((lm & 1) << 3) + lrow) * 128);
    const int acm = lm >> 1;
    const uint32_t bRowOff = (uint32_t)((warpN * 32 + ((lm >> 1) << 3) + lrow) * 128);
    const int bcm = lm & 1;

    for (int kt = 0; kt < NT; kt++) {
        const int s = kt % NSTAGE;
        if (kt < NT - 1) asm volatile("cp.async.wait_group 1;\n" ::: "memory");
        else             asm volatile("cp.async.wait_group 0;\n" ::: "memory");
        __syncthreads();

        if (kt + 1 < NT) stsA((kt + 1) % NSTAGE);
        if (kt + 2 < NT) { ldgA(kt + 2); issueB(kt + 2, (kt + 2) % NSTAGE); }

        const uint32_t abase = sbuf + (uint32_t)s * STAGE_BYTES;
        const uint32_t bbase = abase + 16384u;

#pragma unroll
        for (int slice = 0; slice < 4; slice++) {  // 4 x K=16 covers BKH=64
            const uint32_t aco = (uint32_t)((((slice << 1) + acm) ^ lrow) << 4);
            const uint32_t bco = (uint32_t)((((slice << 1) + bcm) ^ lrow) << 4);
            uint32_t a[4][4];
#pragma unroll
            for (int mi = 0; mi < 4; mi++)
                ldsm_x4(a[mi], abase + aRowOff + (uint32_t)(mi * 2048) + aco);
            uint32_t b[2][4];
#pragma unroll
            for (int pr = 0; pr < 2; pr++)
                ldsm_x4(b[pr], bbase + bRowOff + (uint32_t)(pr * 2048) + bco);
#pragma unroll
            for (int mi = 0; mi < 4; mi++)
#pragma unroll
                for (int ni = 0; ni < 4; ni++) {
                    float* cc = c[mi][ni];
                    const uint32_t b0 = b[ni >> 1][(ni & 1) * 2];
                    const uint32_t b1 = b[ni >> 1][(ni & 1) * 2 + 1];
                    asm volatile(
                        "mma.sync.aligned.m16n8k16.row.col.f32.f16.f16.f32 "
                        "{%0,%1,%2,%3}, {%4,%5,%6,%7}, {%8,%9}, {%0,%1,%2,%3};\n"
                        : "+f"(cc[0]), "+f"(cc[1]), "+f"(cc[2]), "+f"(cc[3])
                        : "r"(a[mi][0]), "r"(a[mi][1]), "r"(a[mi][2]), "r"(a[mi][3]),
                          "r"(b0), "r"(b1));
                }
        }
    }

    // epilogue: float2 stores
#pragma unroll
    for (int mi = 0; mi < 4; mi++) {
        int r0 = bM + warpM * 64 + mi * 16 + (lane >> 2);
#pragma unroll
        for (int ni = 0; ni < 4; ni++) {
            int col = bN + warpN * 32 + ni * 8 + 2 * (lane & 3);
            *(float2*)&out[(size_t)r0 * D_OUT + col]       = make_float2(c[mi][ni][0], c[mi][ni][1]);
            *(float2*)&out[(size_t)(r0 + 8) * D_OUT + col] = make_float2(c[mi][ni][2], c[mi][ni][3]);
        }
    }
}

// ---------------------------------------------------------------------------
// Launch
// ---------------------------------------------------------------------------
extern "C" void kernel_launch(void* const* d_in, const int* in_sizes, int n_in,
                              void* d_out, int out_size) {
    const float* x   = (const float*)d_in[0];  // [4,8192,1024]
    const float* w   = (const float*)d_in[1];  // [1024,1024]
    const float* aw  = (const float*)d_in[2];  // [16,1024]
    const float* bw  = (const float*)d_in[3];  // [1024,16]
    const float* mag = (const float*)d_in[4];  // [1,1024]
    float* out = (float*)d_out;                // [4,8192,1024]

    prep_kernel<<<D_OUT, 256>>>(w, aw, bw, mag);

    static bool attr_set = false;
    if (!attr_set) {
        cudaFuncSetAttribute(gemm_f16, cudaFuncAttributeMaxDynamicSharedMemorySize, SMEM_BYTES);
        cudaFuncSetAttribute(gemm_f16, cudaFuncAttributePreferredSharedMemoryCarveout, 100);
        attr_set = true;
    }
    dim3 grid(D_OUT / BN, M_TOTAL / BM);  // (8, 256): N fastest -> X tile L2 reuse
    gemm_f16<<<grid, 256, SMEM_BYTES>>>(x, out);
}

// round 14
// speedup vs baseline: 1.4226x; 1.4226x over previous
#include <cuda_runtime.h>
#include <cuda_fp16.h>
#include <cstdint>

#define D_IN   1024
#define D_OUT  1024
#define RANK   16
#define M_TOTAL 32768
#define BM 128
#define BN 128
#define BKH 64                    // halves per k-tile (128 B per row)
#define NSTAGE 4
#define NT (D_IN / BKH)           // 16
#define STAGE_BYTES 32768         // A 16 KB + B 16 KB
#define SMEM_BYTES (NSTAGE * STAGE_BYTES + 1024)
#define NCONV (M_TOTAL * D_IN / 8 / 256)   // 16384 conv blocks

// fp16 staging buffers (static __device__ per allocation rules)
__device__ __half g_xh[(size_t)M_TOTAL * D_IN];  // 64 MB
__device__ __half g_wh[(size_t)D_OUT * D_IN];    // 2 MB

// ---------------------------------------------------------------------------
// Fused init: blocks [0, NCONV) convert X fp32->fp16; blocks [NCONV, NCONV+1024)
// build w_half[o][d] = fp16_rn( (mag[o]/||W_o+2B_oA||) * (W+2BA)[o][d] ).
// Overlaps the BW-bound conversion with the latency-bound prep.
// ---------------------------------------------------------------------------
__global__ void init_kernel(const float4* __restrict__ x,
                            const float* __restrict__ W, const float* __restrict__ A,
                            const float* __restrict__ Bw, const float* __restrict__ mag) {
    if (blockIdx.x < NCONV) {
        size_t i = (size_t)blockIdx.x * 256 + threadIdx.x;  // 8 floats per thread
        float4 v0 = x[2 * i];
        float4 v1 = x[2 * i + 1];
        __half2 h0 = __floats2half2_rn(v0.x, v0.y);
        __half2 h1 = __floats2half2_rn(v0.z, v0.w);
        __half2 h2 = __floats2half2_rn(v1.x, v1.y);
        __half2 h3 = __floats2half2_rn(v1.z, v1.w);
        uint4 p;
        p.x = *(uint32_t*)&h0; p.y = *(uint32_t*)&h1;
        p.z = *(uint32_t*)&h2; p.w = *(uint32_t*)&h3;
        ((uint4*)g_xh)[i] = p;
        return;
    }
    int o = blockIdx.x - NCONV;
    __shared__ float bvals[RANK];
    __shared__ float red[8];
    int t = threadIdx.x;  // 256
    if (t < RANK) bvals[t] = 2.0f * Bw[o * RANK + t];
    __syncthreads();

    float we[4];
    float local = 0.f;
#pragma unroll
    for (int i = 0; i < 4; i++) {
        int d = t + i * 256;
        float acc = W[o * D_IN + d];
#pragma unroll
        for (int r = 0; r < RANK; r++) acc = fmaf(bvals[r], A[r * D_IN + d], acc);
        we[i] = acc;
        local = fmaf(acc, acc, local);
    }
#pragma unroll
    for (int s = 16; s; s >>= 1) local += __shfl_xor_sync(0xffffffffu, local, s);
    if ((t & 31) == 0) red[t >> 5] = local;
    __syncthreads();
    if (t < 8) {
        float v = red[t];
#pragma unroll
        for (int s = 4; s; s >>= 1) v += __shfl_xor_sync(0xffu, v, s);
        if (t == 0) red[0] = v;
    }
    __syncthreads();
    float mns = mag[o] / sqrtf(red[0]);
#pragma unroll
    for (int i = 0; i < 4; i++) {
        int d = t + i * 256;
        g_wh[(size_t)o * D_IN + d] = __float2half_rn(mns * we[i]);
    }
}

// ---------------------------------------------------------------------------
// helpers
// ---------------------------------------------------------------------------
__device__ __forceinline__ uint32_t smem_u32(const void* p) {
    uint32_t a;
    asm("{ .reg .u64 t; cvta.to.shared.u64 t, %1; cvt.u32.u64 %0, t; }" : "=r"(a) : "l"(p));
    return a;
}
__device__ __forceinline__ void cp_async16(uint32_t s, const void* g) {
    asm volatile("cp.async.cg.shared.global [%0], [%1], 16;\n" :: "r"(s), "l"(g));
}
__device__ __forceinline__ void ldsm_x4(uint32_t* r, uint32_t addr) {
    asm volatile("ldmatrix.sync.aligned.m8n8.x4.shared.b16 {%0,%1,%2,%3}, [%4];"
                 : "=r"(r[0]), "=r"(r[1]), "=r"(r[2]), "=r"(r[3]) : "r"(addr));
}

// ---------------------------------------------------------------------------
// fp16 GEMM: out[M,N] = Xh[M,K] @ Wh[N,K]^T  (128x128x64 tiles, ldmatrix + m16n8k16)
// 4-stage cp.async + per-slice fragment double-buffering to hide LDSM latency.
// ---------------------------------------------------------------------------
__global__ __launch_bounds__(256) void gemm_f16(float* __restrict__ out) {
    extern __shared__ __align__(16) char smem[];
    const uint32_t sbuf = (smem_u32(smem) + 1023u) & ~1023u;

    const int tid = threadIdx.x;
    const int lane = tid & 31;
    const int warp = tid >> 5;
    const int warpM = warp & 1;   // 2 warps over M: 64 rows each
    const int warpN = warp >> 1;  // 4 warps over N: 32 cols each
    const int bM = blockIdx.y * BM;
    const int bN = blockIdx.x * BN;

    const int lrow = lane & 7;    // row-within-matrix for ldmatrix address
    const int lm = lane >> 3;     // matrix id 0..3

    float c[4][4][4];
#pragma unroll
    for (int i = 0; i < 4; i++)
#pragma unroll
        for (int j = 0; j < 4; j++)
#pragma unroll
            for (int k = 0; k < 4; k++) c[i][j][k] = 0.f;

    // loader: 1024 16B chunks per operand tile (128 rows x 8 chunks), swizzled
    auto issue = [&](int kt, int s) {
        const uint32_t abase = sbuf + (uint32_t)s * STAGE_BYTES;
        const uint32_t bbase = abase + 16384u;
#pragma unroll
        for (int i = 0; i < 4; i++) {
            int cc = tid + i * 256;
            int row = cc >> 3, ch = cc & 7;
            uint32_t off = (uint32_t)(row * 128 + ((ch ^ (row & 7)) << 4));
            cp_async16(abase + off, g_xh + (size_t)(bM + row) * D_IN + kt * BKH + ch * 8);
        }
#pragma unroll
        for (int i = 0; i < 4; i++) {
            int cc = tid + i * 256;
            int row = cc >> 3, ch = cc & 7;
            uint32_t off = (uint32_t)(row * 128 + ((ch ^ (row & 7)) << 4));
            cp_async16(bbase + off, g_wh + (size_t)(bN + row) * D_IN + kt * BKH + ch * 8);
        }
        asm volatile("cp.async.commit_group;\n" ::: "memory");
    };

    issue(0, 0);
    issue(1, 1);
    issue(2, 2);

    // per-lane invariant row offsets (row offsets are multiples of 8 -> row&7 == lrow)
    const uint32_t aRowOff = (uint32_t)((warpM * 64 + ((lm & 1) << 3) + lrow) * 128);
    const int acm = lm >> 1;
    const uint32_t bRowOff = (uint32_t)((warpN * 32 + ((lm >> 1) << 3) + lrow) * 128);
    const int bcm = lm & 1;

    uint32_t a[2][4][4], b[2][2][4];

    auto loadFrags = [&](uint32_t abase, uint32_t bbase, int slice, int buf) {
        const uint32_t aco = (uint32_t)((((slice << 1) + acm) ^ lrow) << 4);
        const uint32_t bco = (uint32_t)((((slice << 1) + bcm) ^ lrow) << 4);
#pragma unroll
        for (int mi = 0; mi < 4; mi++)
            ldsm_x4(a[buf][mi], abase + aRowOff + (uint32_t)(mi * 2048) + aco);
#pragma unroll
        for (int pr = 0; pr < 2; pr++)
            ldsm_x4(b[buf][pr], bbase + bRowOff + (uint32_t)(pr * 2048) + bco);
    };

    for (int kt = 0; kt < NT; kt++) {
        const int s = kt & (NSTAGE - 1);
        asm volatile("cp.async.wait_group 2;\n" ::: "memory");
        __syncthreads();
        if (kt + 3 < NT) issue(kt + 3, (kt + 3) & (NSTAGE - 1));

        const uint32_t abase = sbuf + (uint32_t)s * STAGE_BYTES;
        const uint32_t bbase = abase + 16384u;

        loadFrags(abase, bbase, 0, 0);
#pragma unroll
        for (int slice = 0; slice < 4; slice++) {  // 4 x K=16 covers BKH=64
            const int cur = slice & 1;
            if (slice < 3) loadFrags(abase, bbase, slice + 1, cur ^ 1);
#pragma unroll
            for (int mi = 0; mi < 4; mi++)
#pragma unroll
                for (int ni = 0; ni < 4; ni++) {
                    float* cc = c[mi][ni];
                    const uint32_t b0 = b[cur][ni >> 1][(ni & 1) * 2];
                    const uint32_t b1 = b[cur][ni >> 1][(ni & 1) * 2 + 1];
                    asm volatile(
                        "mma.sync.aligned.m16n8k16.row.col.f32.f16.f16.f32 "
                        "{%0,%1,%2,%3}, {%4,%5,%6,%7}, {%8,%9}, {%0,%1,%2,%3};\n"
                        : "+f"(cc[0]), "+f"(cc[1]), "+f"(cc[2]), "+f"(cc[3])
                        : "r"(a[cur][mi][0]), "r"(a[cur][mi][1]),
                          "r"(a[cur][mi][2]), "r"(a[cur][mi][3]),
                          "r"(b0), "r"(b1));
                }
        }
    }

    // epilogue: float2 stores
#pragma unroll
    for (int mi = 0; mi < 4; mi++) {
        int r0 = bM + warpM * 64 + mi * 16 + (lane >> 2);
#pragma unroll
        for (int ni = 0; ni < 4; ni++) {
            int col = bN + warpN * 32 + ni * 8 + 2 * (lane & 3);
            *(float2*)&out[(size_t)r0 * D_OUT + col]       = make_float2(c[mi][ni][0], c[mi][ni][1]);
            *(float2*)&out[(size_t)(r0 + 8) * D_OUT + col] = make_float2(c[mi][ni][2], c[mi][ni][3]);
        }
    }
}

// ---------------------------------------------------------------------------
// Launch
// ---------------------------------------------------------------------------
extern "C" void kernel_launch(void* const* d_in, const int* in_sizes, int n_in,
                              void* d_out, int out_size) {
    const float* x   = (const float*)d_in[0];  // [4,8192,1024]
    const float* w   = (const float*)d_in[1];  // [1024,1024]
    const float* aw  = (const float*)d_in[2];  // [16,1024]
    const float* bw  = (const float*)d_in[3];  // [1024,16]
    const float* mag = (const float*)d_in[4];  // [1,1024]
    float* out = (float*)d_out;                // [4,8192,1024]

    init_kernel<<<NCONV + D_OUT, 256>>>((const float4*)x, w, aw, bw, mag);

    static bool attr_set = false;
    if (!attr_set) {
        cudaFuncSetAttribute(gemm_f16, cudaFuncAttributeMaxDynamicSharedMemorySize, SMEM_BYTES);
        cudaFuncSetAttribute(gemm_f16, cudaFuncAttributePreferredSharedMemoryCarveout, 100);
        attr_set = true;
    }
    dim3 grid(D_OUT / BN, M_TOTAL / BM);  // (8, 256): N fastest -> X tile L2 reuse
    gemm_f16<<<grid, 256, SMEM_BYTES>>>(out);
}

// round 15
// speedup vs baseline: 1.7546x; 1.2334x over previous
#include <cuda_runtime.h>
#include <cuda_fp16.h>
#include <cstdint>

#define D_IN   1024
#define D_OUT  1024
#define RANK   16
#define M_TOTAL 32768
#define BM 128
#define BN 128
#define BKH 64                    // halves per k-tile (128 B per row)
#define NSTAGE 3
#define NT (D_IN / BKH)           // 16
#define STAGE_BYTES 32768         // A 16 KB + B 16 KB
#define SMEM_BYTES (NSTAGE * STAGE_BYTES + 1024)
#define NCONV (M_TOTAL * D_IN / 8 / 256)   // 16384 conv blocks

// fp16 staging buffers (static __device__ per allocation rules)
__device__ __half g_xh[(size_t)M_TOTAL * D_IN];  // 64 MB
__device__ __half g_wh[(size_t)D_OUT * D_IN];    // 2 MB

// ---------------------------------------------------------------------------
// Fused init: blocks [0, NCONV) convert X fp32->fp16; blocks [NCONV, NCONV+1024)
// build w_half[o][d] = fp16_rn( (mag[o]/||W_o+2B_oA||) * (W+2BA)[o][d] ).
// Overlaps the BW-bound conversion with the latency-bound prep.
// ---------------------------------------------------------------------------
__global__ void init_kernel(const float4* __restrict__ x,
                            const float* __restrict__ W, const float* __restrict__ A,
                            const float* __restrict__ Bw, const float* __restrict__ mag) {
    if (blockIdx.x < NCONV) {
        size_t i = (size_t)blockIdx.x * 256 + threadIdx.x;  // 8 floats per thread
        float4 v0 = x[2 * i];
        float4 v1 = x[2 * i + 1];
        __half2 h0 = __floats2half2_rn(v0.x, v0.y);
        __half2 h1 = __floats2half2_rn(v0.z, v0.w);
        __half2 h2 = __floats2half2_rn(v1.x, v1.y);
        __half2 h3 = __floats2half2_rn(v1.z, v1.w);
        uint4 p;
        p.x = *(uint32_t*)&h0; p.y = *(uint32_t*)&h1;
        p.z = *(uint32_t*)&h2; p.w = *(uint32_t*)&h3;
        ((uint4*)g_xh)[i] = p;
        return;
    }
    int o = blockIdx.x - NCONV;
    __shared__ float bvals[RANK];
    __shared__ float red[8];
    int t = threadIdx.x;  // 256
    if (t < RANK) bvals[t] = 2.0f * Bw[o * RANK + t];
    __syncthreads();

    float we[4];
    float local = 0.f;
#pragma unroll
    for (int i = 0; i < 4; i++) {
        int d = t + i * 256;
        float acc = W[o * D_IN + d];
#pragma unroll
        for (int r = 0; r < RANK; r++) acc = fmaf(bvals[r], A[r * D_IN + d], acc);
        we[i] = acc;
        local = fmaf(acc, acc, local);
    }
#pragma unroll
    for (int s = 16; s; s >>= 1) local += __shfl_xor_sync(0xffffffffu, local, s);
    if ((t & 31) == 0) red[t >> 5] = local;
    __syncthreads();
    if (t < 8) {
        float v = red[t];
#pragma unroll
        for (int s = 4; s; s >>= 1) v += __shfl_xor_sync(0xffu, v, s);
        if (t == 0) red[0] = v;
    }
    __syncthreads();
    float mns = mag[o] / sqrtf(red[0]);
#pragma unroll
    for (int i = 0; i < 4; i++) {
        int d = t + i * 256;
        g_wh[(size_t)o * D_IN + d] = __float2half_rn(mns * we[i]);
    }
}

// ---------------------------------------------------------------------------
// helpers
// ---------------------------------------------------------------------------
__device__ __forceinline__ uint32_t smem_u32(const void* p) {
    uint32_t a;
    asm("{ .reg .u64 t; cvta.to.shared.u64 t, %1; cvt.u32.u64 %0, t; }" : "=r"(a) : "l"(p));
    return a;
}
__device__ __forceinline__ void cp_async16(uint32_t s, const void* g) {
    asm volatile("cp.async.cg.shared.global [%0], [%1], 16;\n" :: "r"(s), "l"(g));
}
__device__ __forceinline__ void ldsm_x4(uint32_t* r, uint32_t addr) {
    asm volatile("ldmatrix.sync.aligned.m8n8.x4.shared.b16 {%0,%1,%2,%3}, [%4];"
                 : "=r"(r[0]), "=r"(r[1]), "=r"(r[2]), "=r"(r[3]) : "r"(addr));
}

// ---------------------------------------------------------------------------
// fp16 GEMM: out[M,N] = Xh[M,K] @ Wh[N,K]^T  (128x128x64 tiles, ldmatrix + m16n8k16)
// Exact R7 configuration: 3-stage cp.async, wait_group 1, plain fragment loads.
// ---------------------------------------------------------------------------
__global__ __launch_bounds__(256) void gemm_f16(float* __restrict__ out) {
    extern __shared__ __align__(16) char smem[];
    const uint32_t sbuf = (smem_u32(smem) + 1023u) & ~1023u;

    const int tid = threadIdx.x;
    const int lane = tid & 31;
    const int warp = tid >> 5;
    const int warpM = warp & 1;   // 2 warps over M: 64 rows each
    const int warpN = warp >> 1;  // 4 warps over N: 32 cols each
    const int bM = blockIdx.y * BM;
    const int bN = blockIdx.x * BN;

    const int lrow = lane & 7;    // row-within-matrix for ldmatrix address
    const int lm = lane >> 3;     // matrix id 0..3

    float c[4][4][4];
#pragma unroll
    for (int i = 0; i < 4; i++)
#pragma unroll
        for (int j = 0; j < 4; j++)
#pragma unroll
            for (int k = 0; k < 4; k++) c[i][j][k] = 0.f;

    // loader: 1024 16B chunks per operand tile (128 rows x 8 chunks), swizzled
    auto issue = [&](int kt, int s) {
        const uint32_t abase = sbuf + (uint32_t)s * STAGE_BYTES;
        const uint32_t bbase = abase + 16384u;
#pragma unroll
        for (int i = 0; i < 4; i++) {
            int cc = tid + i * 256;
            int row = cc >> 3, ch = cc & 7;
            uint32_t off = (uint32_t)(row * 128 + ((ch ^ (row & 7)) << 4));
            cp_async16(abase + off, g_xh + (size_t)(bM + row) * D_IN + kt * BKH + ch * 8);
        }
#pragma unroll
        for (int i = 0; i < 4; i++) {
            int cc = tid + i * 256;
            int row = cc >> 3, ch = cc & 7;
            uint32_t off = (uint32_t)(row * 128 + ((ch ^ (row & 7)) << 4));
            cp_async16(bbase + off, g_wh + (size_t)(bN + row) * D_IN + kt * BKH + ch * 8);
        }
        asm volatile("cp.async.commit_group;\n" ::: "memory");
    };

    issue(0, 0);
    issue(1, 1);

    // per-lane invariant row offsets (row offsets are multiples of 8 -> row&7 == lrow)
    const uint32_t aRowOff = (uint32_t)((warpM * 64 + ((lm & 1) << 3) + lrow) * 128);
    const int acm = lm >> 1;
    const uint32_t bRowOff = (uint32_t)((warpN * 32 + ((lm >> 1) << 3) + lrow) * 128);
    const int bcm = lm & 1;

    for (int kt = 0; kt < NT; kt++) {
        const int s = kt % NSTAGE;
        asm volatile("cp.async.wait_group 1;\n" ::: "memory");
        __syncthreads();
        if (kt + 2 < NT) issue(kt + 2, (kt + 2) % NSTAGE);

        const uint32_t abase = sbuf + (uint32_t)s * STAGE_BYTES;
        const uint32_t bbase = abase + 16384u;

#pragma unroll
        for (int slice = 0; slice < 4; slice++) {  // 4 x K=16 covers BKH=64
            const uint32_t aco = (uint32_t)((((slice << 1) + acm) ^ lrow) << 4);
            const uint32_t bco = (uint32_t)((((slice << 1) + bcm) ^ lrow) << 4);
            uint32_t a[4][4];
#pragma unroll
            for (int mi = 0; mi < 4; mi++)
                ldsm_x4(a[mi], abase + aRowOff + (uint32_t)(mi * 2048) + aco);
            uint32_t b[2][4];
#pragma unroll
            for (int pr = 0; pr < 2; pr++)
                ldsm_x4(b[pr], bbase + bRowOff + (uint32_t)(pr * 2048) + bco);
#pragma unroll
            for (int mi = 0; mi < 4; mi++)
#pragma unroll
                for (int ni = 0; ni < 4; ni++) {
                    float* cc = c[mi][ni];
                    const uint32_t b0 = b[ni >> 1][(ni & 1) * 2];
                    const uint32_t b1 = b[ni >> 1][(ni & 1) * 2 + 1];
                    asm volatile(
                        "mma.sync.aligned.m16n8k16.row.col.f32.f16.f16.f32 "
                        "{%0,%1,%2,%3}, {%4,%5,%6,%7}, {%8,%9}, {%0,%1,%2,%3};\n"
                        : "+f"(cc[0]), "+f"(cc[1]), "+f"(cc[2]), "+f"(cc[3])
                        : "r"(a[mi][0]), "r"(a[mi][1]), "r"(a[mi][2]), "r"(a[mi][3]),
                          "r"(b0), "r"(b1));
                }
        }
    }

    // epilogue: float2 stores
#pragma unroll
    for (int mi = 0; mi < 4; mi++) {
        int r0 = bM + warpM * 64 + mi * 16 + (lane >> 2);
#pragma unroll
        for (int ni = 0; ni < 4; ni++) {
            int col = bN + warpN * 32 + ni * 8 + 2 * (lane & 3);
            *(float2*)&out[(size_t)r0 * D_OUT + col]       = make_float2(c[mi][ni][0], c[mi][ni][1]);
            *(float2*)&out[(size_t)(r0 + 8) * D_OUT + col] = make_float2(c[mi][ni][2], c[mi][ni][3]);
        }
    }
}

// ---------------------------------------------------------------------------
// Launch
// ---------------------------------------------------------------------------
extern "C" void kernel_launch(void* const* d_in, const int* in_sizes, int n_in,
                              void* d_out, int out_size) {
    const float* x   = (const float*)d_in[0];  // [4,8192,1024]
    const float* w   = (const float*)d_in[1];  // [1024,1024]
    const float* aw  = (const float*)d_in[2];  // [16,1024]
    const float* bw  = (const float*)d_in[3];  // [1024,16]
    const float* mag = (const float*)d_in[4];  // [1,1024]
    float* out = (float*)d_out;                // [4,8192,1024]

    init_kernel<<<NCONV + D_OUT, 256>>>((const float4*)x, w, aw, bw, mag);

    static bool attr_set = false;
    if (!attr_set) {
        cudaFuncSetAttribute(gemm_f16, cudaFuncAttributeMaxDynamicSharedMemorySize, SMEM_BYTES);
        cudaFuncSetAttribute(gemm_f16, cudaFuncAttributePreferredSharedMemoryCarveout, 100);
        attr_set = true;
    }
    dim3 grid(D_OUT / BN, M_TOTAL / BM);  // (8, 256): N fastest -> X tile L2 reuse
    gemm_f16<<<grid, 256, SMEM_BYTES>>>(out);
}